// round 6
// baseline (speedup 1.0000x reference)
#include <cuda_runtime.h>
#include <math.h>
#include <float.h>

// Problem constants
#define B_ 8
#define T_ 512
#define D_ 256
#define S_ 64
#define P_ 1024
#define R_ 12
#define N1 (R_ * D_)   // 3072: columns of GEMM1 output, n = r*256 + e

typedef unsigned long long u64;

// Scratch (device globals — no allocation allowed)
__device__ float g_pooled[B_ * S_ * D_];        // [bs][d]        512 KB
__device__ float g_L[B_ * S_ * 2 * R_];         // [bs][h*12+r]   48 KB
__device__ float g_T1[B_ * S_ * N1];            // [bs][r*256+e]  6.3 MB

// Packed fp32x2 FMA (FFMA2) — 2x fp32 throughput, PTX-only on Blackwell.
__device__ __forceinline__ void fma2(u64& d, u64 a, u64 b) {
    asm("fma.rn.f32x2 %0, %1, %2, %0;" : "+l"(d) : "l"(a), "l"(b));
}
__device__ __forceinline__ float2 unpk(u64 v) {
    float2 r;
    asm("mov.b64 {%0, %1}, %2;" : "=f"(r.x), "=f"(r.y) : "l"(v));
    return r;
}

// ---------------------------------------------------------------------------
// Kernel 1: ragged span max-pool + per-span linear terms.
// grid = B*S blocks, 256 threads (thread = feature d).
// ---------------------------------------------------------------------------
__global__ __launch_bounds__(256)
void pool_kernel(const float* __restrict__ enc,
                 const float* __restrict__ Wl,   // [2D, R] row-major
                 const int* __restrict__ starts,
                 const int* __restrict__ lens) {
    int bs  = blockIdx.x;          // b*64 + s
    int b   = bs >> 6;
    int tid = threadIdx.x;

    int st = starts[bs];
    int en = st + lens[bs] + 1;    // exclusive, >= st+1
    if (en > T_) en = T_;

    const float* p = enc + ((size_t)b * T_ + st) * D_ + tid;
    float m = -FLT_MAX;
    for (int t = st; t < en; ++t) { m = fmaxf(m, *p); p += D_; }
    g_pooled[bs * D_ + tid] = m;

    __shared__ float sp[D_];
    sp[tid] = m;
    __syncthreads();

    // 24 outputs: o = h*12 + r.  L1 (h=0) pairs with head via W[0:D],
    // L2 (h=1) pairs with tail via W[D:2D].
    int warp = tid >> 5, lane = tid & 31;
#pragma unroll
    for (int j = 0; j < 3; ++j) {
        int o = warp * 3 + j;          // 0..23
        int h = o / R_;
        int r = o - h * R_;
        float sum = 0.f;
        for (int d = lane; d < D_; d += 32)
            sum += sp[d] * Wl[(h * D_ + d) * R_ + r];
#pragma unroll
        for (int off = 16; off; off >>= 1)
            sum += __shfl_xor_sync(0xffffffffu, sum, off);
        if (lane == 0) g_L[bs * (2 * R_) + o] = sum;
    }
}

// ---------------------------------------------------------------------------
// Kernel 2: GEMM1  T1[(b,s), (r,e)] = sum_d pooled[(b,s), d] * Wb[r, d, e]
// BM=BN=64, BK=32, 256 threads, 4x4 micro-tile done as 4x(2xf32x2) FFMA2.
// A smem tile stored pre-splatted (float2{a,a}) so the inner loop has zero
// packing MOVs: 3x LDS.128 + 8x FMA2 per k-step.
// Register-staged prefetch hides the global-load latency between k-chunks.
// ---------------------------------------------------------------------------
__global__ __launch_bounds__(256)
void gemm1_kernel(const float* __restrict__ Wb) {
    __shared__ __align__(16) float2 As2[32][64];   // [k][m], splatted (16 KB)
    __shared__ __align__(16) float  Bs[32][64];    // [k][n]            (8 KB)

    int tid = threadIdx.x;
    int m0 = blockIdx.y * 64;
    int n0 = blockIdx.x * 64;
    int r  = n0 >> 8;
    int e0 = n0 & 255;
    const float* Bb = Wb + (size_t)r * (D_ * D_) + e0;
    const float* A = g_pooled;

    int ty = tid >> 4, tx = tid & 15;          // 16x16 thread grid
    int ar = tid >> 3, ac = tid & 7;           // A loads
    int br = tid >> 4, bc = tid & 15;          // B loads

    u64 acc[4][2] = {};
    float4 pa[2], pb[2];

    // preload k0 = 0
#pragma unroll
    for (int i = 0; i < 2; ++i) {
        pa[i] = *(const float4*)(A + (size_t)(m0 + ar + i * 32) * D_ + ac * 4);
        pb[i] = *(const float4*)(Bb + (size_t)(br + i * 16) * D_ + bc * 4);
    }

    for (int k0 = 0; k0 < D_; k0 += 32) {
#pragma unroll
        for (int i = 0; i < 2; ++i) {
            int row = ar + i * 32;
            As2[ac * 4 + 0][row] = make_float2(pa[i].x, pa[i].x);
            As2[ac * 4 + 1][row] = make_float2(pa[i].y, pa[i].y);
            As2[ac * 4 + 2][row] = make_float2(pa[i].z, pa[i].z);
            As2[ac * 4 + 3][row] = make_float2(pa[i].w, pa[i].w);
            *(float4*)&Bs[br + i * 16][bc * 4] = pb[i];
        }
        __syncthreads();

        if (k0 + 32 < D_) {
#pragma unroll
            for (int i = 0; i < 2; ++i) {
                pa[i] = *(const float4*)(A + (size_t)(m0 + ar + i * 32) * D_ + k0 + 32 + ac * 4);
                pb[i] = *(const float4*)(Bb + (size_t)(k0 + 32 + br + i * 16) * D_ + bc * 4);
            }
        }

#pragma unroll
        for (int kk = 0; kk < 32; ++kk) {
            ulonglong2 a01 = *(ulonglong2*)&As2[kk][ty * 4];       // splat a0, a1
            ulonglong2 a23 = *(ulonglong2*)&As2[kk][ty * 4 + 2];   // splat a2, a3
            ulonglong2 bb2 = *(ulonglong2*)&Bs[kk][tx * 4];        // (b0,b1),(b2,b3)
            fma2(acc[0][0], a01.x, bb2.x); fma2(acc[0][1], a01.x, bb2.y);
            fma2(acc[1][0], a01.y, bb2.x); fma2(acc[1][1], a01.y, bb2.y);
            fma2(acc[2][0], a23.x, bb2.x); fma2(acc[2][1], a23.x, bb2.y);
            fma2(acc[3][0], a23.y, bb2.x); fma2(acc[3][1], a23.y, bb2.y);
        }
        __syncthreads();
    }

#pragma unroll
    for (int i = 0; i < 4; ++i) {
        float2 c01 = unpk(acc[i][0]);
        float2 c23 = unpk(acc[i][1]);
        *(float4*)(g_T1 + (size_t)(m0 + ty * 4 + i) * N1 + n0 + tx * 4) =
            make_float4(c01.x, c01.y, c23.x, c23.y);
    }
}

// ---------------------------------------------------------------------------
// Kernel 3: GEMM2 + fused score.
// One block per (b,r): G[s,t] = sum_e T1[b,s,r*256+e] * pooled[b,t,e]
// (64x64x256, FFMA2 mainloop). The block's G tile is parked in smem, then the
// same block gathers its batch's 1024 pairs and writes out[b,p,r] directly
// (unique per block -> no atomics). Removes the G round-trip + score kernel.
// ---------------------------------------------------------------------------
__global__ __launch_bounds__(256)
void gemm2_kernel(const float* __restrict__ bias,
                  const int* __restrict__ ph,
                  const int* __restrict__ pt,
                  float* __restrict__ out) {
    int bid = blockIdx.x;                 // b*12 + r
    int b = bid / R_;
    int r = bid - b * R_;

    __shared__ __align__(16) float2 As2[64][64];   // [e][s], splatted (32 KB)
    __shared__ __align__(16) float  Bs[64][64];    // [e][t]            (16 KB)

    int tid = threadIdx.x;
    int ty = tid >> 4, tx = tid & 15;
    int lr = tid >> 2;                    // row 0..63
    int lc = tid & 3;                     // base float4 col group

    const float* Ab = g_T1 + (size_t)b * S_ * N1 + r * D_;   // row s: +s*N1
    const float* Bb = g_pooled + (size_t)b * S_ * D_;        // row t: +t*256

    u64 acc[4][2] = {};

    for (int e0 = 0; e0 < D_; e0 += 64) {
#pragma unroll
        for (int i = 0; i < 4; ++i) {
            int cg = lc + 4 * i;          // 0..15
            float4 v = *(const float4*)(Ab + (size_t)lr * N1 + e0 + cg * 4);
            As2[cg * 4 + 0][lr] = make_float2(v.x, v.x);
            As2[cg * 4 + 1][lr] = make_float2(v.y, v.y);
            As2[cg * 4 + 2][lr] = make_float2(v.z, v.z);
            As2[cg * 4 + 3][lr] = make_float2(v.w, v.w);
            float4 w = *(const float4*)(Bb + lr * D_ + e0 + cg * 4);
            Bs[cg * 4 + 0][lr] = w.x;
            Bs[cg * 4 + 1][lr] = w.y;
            Bs[cg * 4 + 2][lr] = w.z;
            Bs[cg * 4 + 3][lr] = w.w;
        }
        __syncthreads();

#pragma unroll
        for (int kk = 0; kk < 64; ++kk) {
            ulonglong2 a01 = *(ulonglong2*)&As2[kk][ty * 4];
            ulonglong2 a23 = *(ulonglong2*)&As2[kk][ty * 4 + 2];
            ulonglong2 bb2 = *(ulonglong2*)&Bs[kk][tx * 4];
            fma2(acc[0][0], a01.x, bb2.x); fma2(acc[0][1], a01.x, bb2.y);
            fma2(acc[1][0], a01.y, bb2.x); fma2(acc[1][1], a01.y, bb2.y);
            fma2(acc[2][0], a23.x, bb2.x); fma2(acc[2][1], a23.x, bb2.y);
            fma2(acc[3][0], a23.y, bb2.x); fma2(acc[3][1], a23.y, bb2.y);
        }
        __syncthreads();
    }

    // Park G tile in smem (reuse As2 storage), then fused pair-score gather.
    float* sg = (float*)As2;              // needs 16 KB of the 32 KB
#pragma unroll
    for (int i = 0; i < 4; ++i) {
        float2 c01 = unpk(acc[i][0]);
        float2 c23 = unpk(acc[i][1]);
        *(float4*)&sg[(ty * 4 + i) * 64 + tx * 4] =
            make_float4(c01.x, c01.y, c23.x, c23.y);
    }
    __syncthreads();

    float bv = bias[r];
    const float* Lb = g_L + (size_t)b * S_ * (2 * R_);
    const int* phb = ph + (b << 10);
    const int* ptb = pt + (b << 10);
    for (int p = tid; p < P_; p += 256) {
        int h = phb[p];
        int t = ptb[p];
        float sc = sg[h * 64 + t] + Lb[h * 24 + r] + Lb[t * 24 + 12 + r] + bv;
        out[(size_t)((b << 10) + p) * R_ + r] = 1.f / (1.f + __expf(-sc));
    }
}

// ---------------------------------------------------------------------------
// Launch.  Inputs in metadata order:
// 0 encoded f32 [8,512,256]   1 W_linear f32 [512,12]   2 b_linear f32 [12]
// 3 W_bilinear f32 [12,256,256]
// 4 span_starts i32 [8,64]    5 span_lens i32 [8,64]
// 6 pair_head i32 [8,1024]    7 pair_tail i32 [8,1024]
// Output f32 [8,1024,12].
// ---------------------------------------------------------------------------
extern "C" void kernel_launch(void* const* d_in, const int* in_sizes, int n_in,
                              void* d_out, int out_size) {
    const float* enc = (const float*)d_in[0];
    const float* Wl  = (const float*)d_in[1];
    const float* bl  = (const float*)d_in[2];
    const float* Wb  = (const float*)d_in[3];
    const int* sst   = (const int*)d_in[4];
    const int* sln   = (const int*)d_in[5];
    const int* ph    = (const int*)d_in[6];
    const int* pt    = (const int*)d_in[7];
    float* out = (float*)d_out;

    pool_kernel<<<B_ * S_, 256>>>(enc, Wl, sst, sln);
    gemm1_kernel<<<dim3(N1 / 64, (B_ * S_) / 64), 256>>>(Wb);
    gemm2_kernel<<<B_ * R_, 256>>>(bl, ph, pt, out);
}

// round 7
// speedup vs baseline: 1.2169x; 1.2169x over previous
#include <cuda_runtime.h>
#include <math.h>
#include <float.h>

// Problem constants
#define B_ 8
#define T_ 512
#define D_ 256
#define S_ 64
#define P_ 1024
#define R_ 12
#define N1 (R_ * D_)   // 3072: columns of GEMM1 output, n = r*256 + e

// Scratch (device globals — no allocation allowed)
__device__ float g_pooled[B_ * S_ * D_];        // [bs][d]        512 KB
__device__ float g_L[B_ * S_ * 2 * R_];         // [bs][h*12+r]   48 KB
__device__ float g_T1[B_ * S_ * N1];            // [bs][r*256+e]  6.3 MB

// ---------------------------------------------------------------------------
// Kernel 1: ragged span max-pool + per-span linear terms.
// grid = B*S blocks, 256 threads (thread = feature d).
// Wl is staged into smem with coalesced float4 loads; the strided reads of
// the linear phase then hit shared memory (4-way conflicts) instead of
// generating 32 L1 sectors per warp-load (R6 profile: L1 25% busy).
// ---------------------------------------------------------------------------
__global__ __launch_bounds__(256)
void pool_kernel(const float* __restrict__ enc,
                 const float* __restrict__ Wl,   // [2D, R] row-major
                 const int* __restrict__ starts,
                 const int* __restrict__ lens) {
    __shared__ float sp[D_];
    __shared__ float sWl[2 * D_ * R_];           // 6144 floats = 24 KB

    int bs  = blockIdx.x;          // b*64 + s
    int b   = bs >> 6;
    int tid = threadIdx.x;

    // coalesced Wl copy: 1536 float4 / 256 threads = 6 each
    {
        const float4* w4 = (const float4*)Wl;
        float4* s4 = (float4*)sWl;
#pragma unroll
        for (int i = 0; i < 6; ++i) s4[tid + i * 256] = w4[tid + i * 256];
    }

    int st = starts[bs];
    int en = st + lens[bs] + 1;    // exclusive, >= st+1
    if (en > T_) en = T_;

    const float* p = enc + ((size_t)b * T_ + st) * D_ + tid;
    float m = -FLT_MAX;
    for (int t = st; t < en; ++t) { m = fmaxf(m, *p); p += D_; }
    g_pooled[bs * D_ + tid] = m;
    sp[tid] = m;
    __syncthreads();

    // 24 outputs: o = h*12 + r.  L1 (h=0) pairs with head via W[0:D],
    // L2 (h=1) pairs with tail via W[D:2D].
    int warp = tid >> 5, lane = tid & 31;
#pragma unroll
    for (int j = 0; j < 3; ++j) {
        int o = warp * 3 + j;          // 0..23
        int h = o / R_;
        int r = o - h * R_;
        float sum = 0.f;
#pragma unroll
        for (int d = lane; d < D_; d += 32)
            sum += sp[d] * sWl[(h * D_ + d) * R_ + r];
#pragma unroll
        for (int off = 16; off; off >>= 1)
            sum += __shfl_xor_sync(0xffffffffu, sum, off);
        if (lane == 0) g_L[bs * (2 * R_) + o] = sum;
    }
}

// ---------------------------------------------------------------------------
// Kernel 2: GEMM1  T1[(b,s), (r,e)] = sum_d pooled[(b,s), d] * Wb[r, d, e]
// BM=BN=64, BK=32, 256 threads, 4x4 scalar-FFMA micro-tile (proven R5 form;
// runs at ~78% of the scalar fp32 pipe roofline).
// ---------------------------------------------------------------------------
__global__ __launch_bounds__(256)
void gemm1_kernel(const float* __restrict__ Wb) {
    __shared__ float As[32][64];   // [k][m]
    __shared__ float Bs[32][64];   // [k][n]

    int tid = threadIdx.x;
    int m0 = blockIdx.y * 64;
    int n0 = blockIdx.x * 64;
    int r  = n0 >> 8;
    int e0 = n0 & 255;
    const float* Bbase = Wb + (size_t)r * (D_ * D_) + e0;
    const float* A = g_pooled;

    int ty = tid >> 4, tx = tid & 15;          // 16x16 thread grid
    int ar = tid >> 3, ac = tid & 7;           // A loads
    int br = tid >> 4, bc = tid & 15;          // B loads

    float acc[4][4] = {};

    for (int k0 = 0; k0 < D_; k0 += 32) {
#pragma unroll
        for (int i = 0; i < 2; ++i) {
            int row = ar + i * 32;
            float4 v = *(const float4*)(A + (m0 + row) * D_ + k0 + ac * 4);
            As[ac * 4 + 0][row] = v.x;
            As[ac * 4 + 1][row] = v.y;
            As[ac * 4 + 2][row] = v.z;
            As[ac * 4 + 3][row] = v.w;
        }
#pragma unroll
        for (int i = 0; i < 2; ++i) {
            int row = br + i * 16;
            float4 v = *(const float4*)(Bbase + (size_t)(k0 + row) * D_ + bc * 4);
            *(float4*)&Bs[row][bc * 4] = v;
        }
        __syncthreads();

#pragma unroll
        for (int kk = 0; kk < 32; ++kk) {
            float4 a = *(float4*)&As[kk][ty * 4];
            float4 b = *(float4*)&Bs[kk][tx * 4];
            float av[4] = {a.x, a.y, a.z, a.w};
            float bv[4] = {b.x, b.y, b.z, b.w};
#pragma unroll
            for (int i = 0; i < 4; ++i)
#pragma unroll
                for (int j = 0; j < 4; ++j)
                    acc[i][j] += av[i] * bv[j];
        }
        __syncthreads();
    }

#pragma unroll
    for (int i = 0; i < 4; ++i) {
        float4 v = make_float4(acc[i][0], acc[i][1], acc[i][2], acc[i][3]);
        *(float4*)(g_T1 + (size_t)(m0 + ty * 4 + i) * N1 + n0 + tx * 4) = v;
    }
}

// ---------------------------------------------------------------------------
// Kernel 3: GEMM2 + fused score, t-split x4 for full-chip occupancy.
// grid = B*R*4 = 384 blocks (was 96, leaving 52 SMs idle).
// Block (b, r, tq) computes G[s, t] = sum_e T1[b,s,r*256+e] * pooled[b,t,e]
// for s in [0,64), t in [t0, t0+16), k=256; scalar FFMA 4x1 micro-tile.
// The 64x16 G subtile is parked in smem, then the block gathers the pairs
// whose tail falls in its t-range and writes out[b,p,r] directly (ranges
// are disjoint -> no atomics). Deletes the separate score kernel and the
// 1.6 MB G round-trip.
// ---------------------------------------------------------------------------
__global__ __launch_bounds__(256)
void gemm2_kernel(const float* __restrict__ bias,
                  const int* __restrict__ ph,
                  const int* __restrict__ pt,
                  float* __restrict__ out) {
    int bid = blockIdx.x;                 // b*48 + r*4 + tq
    int b   = bid / 48;
    int rem = bid - b * 48;
    int r   = rem >> 2;
    int t0  = (rem & 3) << 4;

    __shared__ float As[64][64];          // [e][s]  16 KB
    __shared__ float Bs[64][17];          // [e][t]  padded: kills 16-way STS conflict
    __shared__ float sg[64 * 16];         // G subtile 4 KB

    int tid = threadIdx.x;
    int ty = tid >> 4, tx = tid & 15;     // compute: s-group, t
    int lr = tid >> 2, lc = tid & 3;      // A loads: row s, f4 col group base
    int tt = tid >> 4, ec = tid & 15;     // B loads: t, f4 col group

    const float* Ab = g_T1 + (size_t)b * S_ * N1 + r * D_;       // row s: +s*N1
    const float* Bb = g_pooled + ((size_t)b * S_ + t0) * D_;     // row t: +t*256

    float acc[4] = {};

    for (int e0 = 0; e0 < D_; e0 += 64) {
#pragma unroll
        for (int i = 0; i < 4; ++i) {
            int cg = lc + 4 * i;          // 0..15
            float4 v = *(const float4*)(Ab + (size_t)lr * N1 + e0 + cg * 4);
            As[cg * 4 + 0][lr] = v.x;
            As[cg * 4 + 1][lr] = v.y;
            As[cg * 4 + 2][lr] = v.z;
            As[cg * 4 + 3][lr] = v.w;
        }
        {
            float4 w = *(const float4*)(Bb + tt * D_ + e0 + ec * 4);
            Bs[ec * 4 + 0][tt] = w.x;
            Bs[ec * 4 + 1][tt] = w.y;
            Bs[ec * 4 + 2][tt] = w.z;
            Bs[ec * 4 + 3][tt] = w.w;
        }
        __syncthreads();

#pragma unroll
        for (int kk = 0; kk < 64; ++kk) {
            float4 a = *(float4*)&As[kk][ty * 4];
            float bv = Bs[kk][tx];
            acc[0] += a.x * bv;
            acc[1] += a.y * bv;
            acc[2] += a.z * bv;
            acc[3] += a.w * bv;
        }
        __syncthreads();
    }

    // Park G subtile, then fused pair-score gather.
#pragma unroll
    for (int i = 0; i < 4; ++i)
        sg[(ty * 4 + i) * 16 + tx] = acc[i];
    __syncthreads();

    float bv = bias[r];
    const float* Lb = g_L + (size_t)b * S_ * (2 * R_);
    const int* phb = ph + (b << 10);
    const int* ptb = pt + (b << 10);
    for (int p = tid; p < P_; p += 256) {
        int t = ptb[p];
        unsigned dt = (unsigned)(t - t0);
        if (dt < 16u) {
            int h = phb[p];
            float sc = sg[h * 16 + dt] + Lb[h * 24 + r] + Lb[t * 24 + 12 + r] + bv;
            out[(size_t)((b << 10) + p) * R_ + r] = 1.f / (1.f + __expf(-sc));
        }
    }
}

// ---------------------------------------------------------------------------
// Launch.  Inputs in metadata order:
// 0 encoded f32 [8,512,256]   1 W_linear f32 [512,12]   2 b_linear f32 [12]
// 3 W_bilinear f32 [12,256,256]
// 4 span_starts i32 [8,64]    5 span_lens i32 [8,64]
// 6 pair_head i32 [8,1024]    7 pair_tail i32 [8,1024]
// Output f32 [8,1024,12].
// ---------------------------------------------------------------------------
extern "C" void kernel_launch(void* const* d_in, const int* in_sizes, int n_in,
                              void* d_out, int out_size) {
    const float* enc = (const float*)d_in[0];
    const float* Wl  = (const float*)d_in[1];
    const float* bl  = (const float*)d_in[2];
    const float* Wb  = (const float*)d_in[3];
    const int* sst   = (const int*)d_in[4];
    const int* sln   = (const int*)d_in[5];
    const int* ph    = (const int*)d_in[6];
    const int* pt    = (const int*)d_in[7];
    float* out = (float*)d_out;

    pool_kernel<<<B_ * S_, 256>>>(enc, Wl, sst, sln);
    gemm1_kernel<<<dim3(N1 / 64, (B_ * S_) / 64), 256>>>(Wb);
    gemm2_kernel<<<B_ * R_ * 4, 256>>>(bl, ph, pt, out);
}